// round 1
// baseline (speedup 1.0000x reference)
#include <cuda_runtime.h>
#include <mma.h>

using namespace nvcuda;

// Problem constants
#define MBLK 64
#define PDIM 256
#define BATCH 4096
#define ROWSTRIDE (MBLK * PDIM)   // 16384 floats per batch row

// Tiling
#define BM 64     // batch rows per CTA
#define BN 256    // full output block width per CTA (avoids re-reading x)
#define BK 16     // K chunk (2 tf32 k=8 steps)

// 8 warps: 2 along M (32 rows each), 4 along N (64 cols each)
__global__ __launch_bounds__(256, 2)
void bxdiag_tf32_kernel(const float* __restrict__ x,
                        const float* __restrict__ Wd,
                        const float* __restrict__ Wu,
                        const float* __restrict__ Wl,
                        const float* __restrict__ Wtr,
                        const float* __restrict__ Wbl,
                        float* __restrict__ out)
{
    const int bt  = blockIdx.x;   // batch tile index (0..63)
    const int i   = blockIdx.y;   // output block index (0..63)
    const int tid = threadIdx.x;
    const int w   = tid >> 5;
    const int wm  = w & 1;        // warp row  (0..1)  -> 32 M-rows each
    const int wn  = w >> 1;       // warp col  (0..3)  -> 64 N-cols each

    __shared__ __align__(16) float sA[BM * BK];   // [row][k], ld = BK
    __shared__ __align__(16) float sB[BN * BK];   // [n][k]  == col-major [k][n], ld = BK

    wmma::fragment<wmma::accumulator, 16, 16, 8, float> acc[2][4];
    #pragma unroll
    for (int a = 0; a < 2; ++a)
        #pragma unroll
        for (int b = 0; b < 4; ++b)
            wmma::fill_fragment(acc[a][b], 0.0f);

    const int row0 = bt * BM;

    // Three K-segments: diagonal, upper(+periodic bl), lower(+periodic tr)
    #pragma unroll 1
    for (int s = 0; s < 3; ++s) {
        int j;
        const float* W;
        if (s == 0) {
            j = i;
            W = Wd + (size_t)i * PDIM * PDIM;
        } else if (s == 1) {
            j = (i + 1) & (MBLK - 1);
            W = (i < MBLK - 1) ? (Wu + (size_t)i * PDIM * PDIM) : Wbl;
        } else {
            j = (i + MBLK - 1) & (MBLK - 1);
            W = (i > 0) ? (Wl + (size_t)(i - 1) * PDIM * PDIM) : Wtr;
        }
        const float* xsrc = x + (size_t)row0 * ROWSTRIDE + j * PDIM;

        #pragma unroll 1
        for (int k0 = 0; k0 < PDIM; k0 += BK) {
            // --- stage A: 64 rows x 16 k  (one float4 per thread) ---
            {
                int r = tid >> 2;
                int c = (tid & 3) << 2;
                float4 v = *reinterpret_cast<const float4*>(
                    xsrc + (size_t)r * ROWSTRIDE + k0 + c);
                *reinterpret_cast<float4*>(&sA[r * BK + c]) = v;
            }
            // --- stage B: 256 n x 16 k  (four float4 per thread) ---
            // W is [q][p] row-major; element (k, n) sits at W[n*PDIM + k],
            // which is exactly col-major [k][n] with ld = PDIM -> restage
            // contiguous 16-float runs per n into sB with ld = BK.
            #pragma unroll
            for (int rep = 0; rep < 4; ++rep) {
                int n  = rep * 64 + (tid >> 2);
                int kq = (tid & 3) << 2;
                float4 v = *reinterpret_cast<const float4*>(W + n * PDIM + k0 + kq);
                *reinterpret_cast<float4*>(&sB[n * BK + kq]) = v;
            }
            __syncthreads();

            #pragma unroll
            for (int kk = 0; kk < BK; kk += 8) {
                wmma::fragment<wmma::matrix_a, 16, 16, 8,
                               wmma::precision::tf32, wmma::row_major> af[2];
                wmma::fragment<wmma::matrix_b, 16, 16, 8,
                               wmma::precision::tf32, wmma::col_major> bf[4];
                #pragma unroll
                for (int mi = 0; mi < 2; ++mi) {
                    wmma::load_matrix_sync(af[mi], &sA[(wm * 32 + mi * 16) * BK + kk], BK);
                    #pragma unroll
                    for (int t = 0; t < af[mi].num_elements; ++t)
                        af[mi].x[t] = wmma::__float_to_tf32(af[mi].x[t]);
                }
                #pragma unroll
                for (int ni = 0; ni < 4; ++ni) {
                    wmma::load_matrix_sync(bf[ni], &sB[(wn * 64 + ni * 16) * BK + kk], BK);
                    #pragma unroll
                    for (int t = 0; t < bf[ni].num_elements; ++t)
                        bf[ni].x[t] = wmma::__float_to_tf32(bf[ni].x[t]);
                }
                #pragma unroll
                for (int mi = 0; mi < 2; ++mi)
                    #pragma unroll
                    for (int ni = 0; ni < 4; ++ni)
                        wmma::mma_sync(acc[mi][ni], af[mi], bf[ni], acc[mi][ni]);
            }
            __syncthreads();
        }
    }

    // --- epilogue: store 64x256 tile of out block i ---
    float* obase = out + (size_t)row0 * ROWSTRIDE + i * PDIM;
    #pragma unroll
    for (int mi = 0; mi < 2; ++mi)
        #pragma unroll
        for (int ni = 0; ni < 4; ++ni)
            wmma::store_matrix_sync(
                obase + (size_t)(wm * 32 + mi * 16) * ROWSTRIDE + (wn * 64 + ni * 16),
                acc[mi][ni], ROWSTRIDE, wmma::mem_row_major);
}

extern "C" void kernel_launch(void* const* d_in, const int* in_sizes, int n_in,
                              void* d_out, int out_size)
{
    const float* x   = (const float*)d_in[0];
    const float* Wd  = (const float*)d_in[1];
    const float* Wu  = (const float*)d_in[2];
    const float* Wl  = (const float*)d_in[3];
    const float* Wtr = (const float*)d_in[4];
    const float* Wbl = (const float*)d_in[5];
    float* out = (float*)d_out;

    dim3 grid(BATCH / BM, MBLK);   // 64 x 64 = 4096 CTAs
    dim3 block(256);
    bxdiag_tf32_kernel<<<grid, block>>>(x, Wd, Wu, Wl, Wtr, Wbl, out);
}

// round 3
// speedup vs baseline: 4.1955x; 4.1955x over previous
#include <cuda_runtime.h>
#include <cstdint>

#define MBLK 64
#define PDIM 256
#define BATCH 4096
#define ROWSTRIDE 16384          // MBLK*PDIM floats per batch row

#define TILE_M 128               // batch rows per CTA
#define TILE_N 256               // full output block width
#define BK 32                    // K floats per pipeline chunk
#define NCHUNK 24                // 3 segments * 256/32
#define NSTAGE 3

#define ASTRIDE 36               // padded row stride (floats) -> conflict-free frag LDS
#define SA_FLOATS (TILE_M * ASTRIDE)     // 4608
#define SB_FLOATS (TILE_N * ASTRIDE)     // 9216
#define STAGE_FLOATS (SA_FLOATS + SB_FLOATS)   // 13824
#define SMEM_BYTES (STAGE_FLOATS * 4 * NSTAGE) // 165888

__device__ __forceinline__ uint32_t smem_u32(const void* p) {
    uint32_t a;
    asm("{ .reg .u64 t; cvta.to.shared.u64 t, %1; cvt.u32.u64 %0, t; }" : "=r"(a) : "l"(p));
    return a;
}

__device__ __forceinline__ void cp16(uint32_t dst, const void* src) {
    asm volatile("cp.async.cg.shared.global [%0], [%1], 16;\n" :: "r"(dst), "l"(src));
}
__device__ __forceinline__ void cp_commit() {
    asm volatile("cp.async.commit_group;\n" ::: "memory");
}
template <int N>
__device__ __forceinline__ void cp_wait() {
    asm volatile("cp.async.wait_group %0;\n" :: "n"(N) : "memory");
}

__device__ __forceinline__ void mma8(float* c,
                                     float a0, float a1, float a2, float a3,
                                     float b0, float b1) {
    asm volatile(
        "mma.sync.aligned.m16n8k8.row.col.f32.tf32.tf32.f32 "
        "{%0,%1,%2,%3}, {%4,%5,%6,%7}, {%8,%9}, {%0,%1,%2,%3};\n"
        : "+f"(c[0]), "+f"(c[1]), "+f"(c[2]), "+f"(c[3])
        : "r"(__float_as_uint(a0)), "r"(__float_as_uint(a1)),
          "r"(__float_as_uint(a2)), "r"(__float_as_uint(a3)),
          "r"(__float_as_uint(b0)), "r"(__float_as_uint(b1)));
}

// Resolve segment s of output block i -> (source block j, weight block W)
__device__ __forceinline__ const float* seg_w(int s, int i,
                                              const float* Wd, const float* Wu,
                                              const float* Wl, const float* Wtr,
                                              const float* Wbl, int& j) {
    if (s == 0) { j = i;            return Wd + (size_t)i * (PDIM * PDIM); }
    if (s == 1) { j = (i + 1) & 63; return (i < 63) ? Wu + (size_t)i * (PDIM * PDIM) : Wbl; }
    j = (i + 63) & 63;              return (i > 0) ? Wl + (size_t)(i - 1) * (PDIM * PDIM) : Wtr;
}

__global__ void __launch_bounds__(256, 1)
bxdiag_mma_kernel(const float* __restrict__ x,
                  const float* __restrict__ Wd,
                  const float* __restrict__ Wu,
                  const float* __restrict__ Wl,
                  const float* __restrict__ Wtr,
                  const float* __restrict__ Wbl,
                  float* __restrict__ out)
{
    extern __shared__ __align__(128) float smem[];
    const uint32_t sbase = smem_u32(smem);

    const int tid = threadIdx.x;
    const int wid = tid >> 5;
    const int lid = tid & 31;
    const int wm  = wid & 1;       // 0..1 : 64-row half
    const int wn  = wid >> 1;      // 0..3 : 64-col quarter
    const int bt  = blockIdx.x;    // batch tile 0..31
    const int i   = blockIdx.y;    // output block 0..63
    const int row0 = bt * TILE_M;

    // ---- stage issuer (all 256 threads: 4 A-chunks + 8 B-chunks of 16B) ----
    auto issue_stage = [&](int c) {
        const int s  = c >> 3;
        const int k0 = (c & 7) * BK;
        int j;
        const float* W = seg_w(s, i, Wd, Wu, Wl, Wtr, Wbl, j);
        const float* xsrc = x + (size_t)row0 * ROWSTRIDE + j * PDIM + k0;
        const float* wsrc = W + k0;
        const uint32_t ab = sbase + (uint32_t)((c % NSTAGE) * STAGE_FLOATS) * 4u;
        const uint32_t bb = ab + SA_FLOATS * 4u;
        #pragma unroll
        for (int it = 0; it < 4; ++it) {           // A: 128 rows x 8 chunks
            const int ch = tid + it * 256;
            const int r = ch >> 3, cc = ch & 7;
            cp16(ab + (uint32_t)(r * ASTRIDE + cc * 4) * 4u,
                 xsrc + (size_t)r * ROWSTRIDE + cc * 4);
        }
        #pragma unroll
        for (int it = 0; it < 8; ++it) {           // B: 256 rows x 8 chunks
            const int ch = tid + it * 256;
            const int r = ch >> 3, cc = ch & 7;
            cp16(bb + (uint32_t)(r * ASTRIDE + cc * 4) * 4u,
                 wsrc + r * PDIM + cc * 4);
        }
    };

    float acc[4][8][4];
    #pragma unroll
    for (int mt = 0; mt < 4; ++mt)
        #pragma unroll
        for (int nt = 0; nt < 8; ++nt)
            #pragma unroll
            for (int q = 0; q < 4; ++q)
                acc[mt][nt][q] = 0.0f;

    // ---- prologue: fill 2 stages ----
    issue_stage(0); cp_commit();
    issue_stage(1); cp_commit();

    const int g  = lid >> 2;   // 0..7
    const int tg = lid & 3;    // 0..3

    #pragma unroll 1
    for (int c = 0; c < NCHUNK; ++c) {
        if (c + 2 < NCHUNK) issue_stage(c + 2);
        cp_commit();
        cp_wait<2>();          // chunk c resident
        __syncthreads();

        const float* sAb = smem + (c % NSTAGE) * STAGE_FLOATS;
        const float* sBb = sAb + SA_FLOATS;
        const float* arow = sAb + (wm * 64 + g) * ASTRIDE + tg;
        const float* brow = sBb + (wn * 64 + g) * ASTRIDE + tg;

        #pragma unroll
        for (int k8 = 0; k8 < BK / 8; ++k8) {
            const float* ap = arow + k8 * 8;
            const float* bp = brow + k8 * 8;
            float a[4][4], b[8][2];
            #pragma unroll
            for (int mt = 0; mt < 4; ++mt) {
                a[mt][0] = ap[(mt * 16)     * ASTRIDE];
                a[mt][1] = ap[(mt * 16 + 8) * ASTRIDE];
                a[mt][2] = ap[(mt * 16)     * ASTRIDE + 4];
                a[mt][3] = ap[(mt * 16 + 8) * ASTRIDE + 4];
            }
            #pragma unroll
            for (int nt = 0; nt < 8; ++nt) {
                b[nt][0] = bp[(nt * 8) * ASTRIDE];
                b[nt][1] = bp[(nt * 8) * ASTRIDE + 4];
            }
            #pragma unroll
            for (int mt = 0; mt < 4; ++mt)
                #pragma unroll
                for (int nt = 0; nt < 8; ++nt)
                    mma8(acc[mt][nt], a[mt][0], a[mt][1], a[mt][2], a[mt][3],
                         b[nt][0], b[nt][1]);
        }
        __syncthreads();
    }

    // ---- epilogue: direct STG.64, C-fragment layout ----
    float* ob = out + (size_t)row0 * ROWSTRIDE + i * PDIM;
    #pragma unroll
    for (int mt = 0; mt < 4; ++mt) {
        #pragma unroll
        for (int nt = 0; nt < 8; ++nt) {
            const int r0 = wm * 64 + mt * 16 + g;
            const int cc = wn * 64 + nt * 8 + tg * 2;
            float2 v0 = make_float2(acc[mt][nt][0], acc[mt][nt][1]);
            float2 v1 = make_float2(acc[mt][nt][2], acc[mt][nt][3]);
            *reinterpret_cast<float2*>(ob + (size_t)r0 * ROWSTRIDE + cc) = v0;
            *reinterpret_cast<float2*>(ob + (size_t)(r0 + 8) * ROWSTRIDE + cc) = v1;
        }
    }
}

extern "C" void kernel_launch(void* const* d_in, const int* in_sizes, int n_in,
                              void* d_out, int out_size)
{
    const float* x   = (const float*)d_in[0];
    const float* Wd  = (const float*)d_in[1];
    const float* Wu  = (const float*)d_in[2];
    const float* Wl  = (const float*)d_in[3];
    const float* Wtr = (const float*)d_in[4];
    const float* Wbl = (const float*)d_in[5];
    float* out = (float*)d_out;

    cudaFuncSetAttribute(bxdiag_mma_kernel,
                         cudaFuncAttributeMaxDynamicSharedMemorySize, SMEM_BYTES);
    dim3 grid(BATCH / TILE_M, MBLK);   // 32 x 64 = 2048 CTAs
    bxdiag_mma_kernel<<<grid, 256, SMEM_BYTES>>>(x, Wd, Wu, Wl, Wtr, Wbl, out);
}